// round 1
// baseline (speedup 1.0000x reference)
#include <cuda_runtime.h>

#define SEQ   4096
#define DH    2048
#define DOUT  1024
#define LN_EPS 1e-5f

// Scratch (allocation-free rule: __device__ globals)
__device__ float g_gate_norm[(size_t)SEQ * DH];   // 32 MB
__device__ float g_gated[(size_t)SEQ * DH];       // 32 MB

// ---------------------------------------------------------------------------
// Kernel 1: LayerNorm (scale only) of the gate half: gate = x[:, DH:2*DH]
// One block (256 threads) per row.
// ---------------------------------------------------------------------------
__global__ __launch_bounds__(256) void ln_kernel(const float* __restrict__ x,
                                                 const float* __restrict__ ln_scale)
{
    const int row = blockIdx.x;
    const int t   = threadIdx.x;
    const float* g = x + (size_t)row * (2 * DH) + DH;

    float v[8];
    float sum = 0.f, sumsq = 0.f;
#pragma unroll
    for (int i = 0; i < 8; i++) {
        float val = g[t + i * 256];
        v[i] = val;
        sum += val;
        sumsq += val * val;
    }

    __shared__ float s1[8], s2[8];
#pragma unroll
    for (int o = 16; o > 0; o >>= 1) {
        sum   += __shfl_xor_sync(0xFFFFFFFFu, sum, o);
        sumsq += __shfl_xor_sync(0xFFFFFFFFu, sumsq, o);
    }
    const int w = t >> 5, l = t & 31;
    if (l == 0) { s1[w] = sum; s2[w] = sumsq; }
    __syncthreads();
    if (w == 0) {
        sum   = (l < 8) ? s1[l] : 0.f;
        sumsq = (l < 8) ? s2[l] : 0.f;
#pragma unroll
        for (int o = 4; o > 0; o >>= 1) {
            sum   += __shfl_xor_sync(0xFFFFFFFFu, sum, o);
            sumsq += __shfl_xor_sync(0xFFFFFFFFu, sumsq, o);
        }
        if (l == 0) { s1[0] = sum; s2[0] = sumsq; }
    }
    __syncthreads();

    const float mean = s1[0] * (1.0f / DH);
    const float var  = s2[0] * (1.0f / DH) - mean * mean;
    const float inv  = rsqrtf(var + LN_EPS);

#pragma unroll
    for (int i = 0; i < 8; i++) {
        const int j = t + i * 256;
        g_gate_norm[(size_t)row * DH + j] = (v[i] - mean) * inv * ln_scale[j];
    }
}

// ---------------------------------------------------------------------------
// Tiled fp32 GEMM, 128x128x16 tiles, 256 threads, 8x8 per thread.
// MODE 0 (spatial): C[m,d] = xh[m,d] * ( sum_{n<=m} W[m,n]*G[n,d] + bias[m] )
//                   A=W (lda=4096), B=g_gate_norm (ldb=2048), C=g_gated
//                   K-loop truncated at m0+BM (triangular), per-element tril mask
// MODE 1 (proj):    C[m,j] = sum_d gated[m,d]*Pw[d,j] + pb[j]
//                   A=g_gated (lda=2048), B=proj_w (ldb=1024), C=out
// ---------------------------------------------------------------------------
static constexpr int BM = 128, BN = 128, BK = 16;

template <int MODE>
__global__ __launch_bounds__(256) void gemm_kernel(
    const float* __restrict__ A, const float* __restrict__ B,
    float* __restrict__ C,
    const float* __restrict__ xh_or_pb,   // MODE0: x (row stride 2*DH), MODE1: proj_b
    const float* __restrict__ bias)       // MODE0: spatial_biases, MODE1: unused
{
    constexpr int Kdim = (MODE == 0) ? SEQ : DH;
    constexpr int lda  = (MODE == 0) ? SEQ : DH;
    constexpr int ldb  = (MODE == 0) ? DH : DOUT;
    constexpr int ldc  = ldb;

    __shared__ float As[BK][BM + 4];
    __shared__ float Bs[BK][BN + 4];

    const int tid = threadIdx.x;
    const int tx = tid & 15;        // 0..15 -> 8 cols each
    const int ty = tid >> 4;        // 0..15 -> 8 rows each
    const int m0 = blockIdx.y * BM;
    const int n0 = blockIdx.x * BN;

    float acc[8][8];
#pragma unroll
    for (int i = 0; i < 8; i++)
#pragma unroll
        for (int j = 0; j < 8; j++) acc[i][j] = 0.f;

    const int kend = (MODE == 0) ? (m0 + BM) : Kdim;

    for (int k0 = 0; k0 < kend; k0 += BK) {
        // ---- load A tile (BM x BK) transposed into As[k][m] ----
#pragma unroll
        for (int i = 0; i < 2; i++) {
            const int idx = tid + i * 256;          // 0..511 float4 slots
            const int r   = idx >> 2;               // 0..127
            const int c4  = (idx & 3) << 2;         // 0,4,8,12
            const int gm  = m0 + r;
            const int gk  = k0 + c4;
            float4 va = *(const float4*)(A + (size_t)gm * lda + gk);
            if (MODE == 0) {                        // tril mask: zero where k > m
                if (gk + 0 > gm) va.x = 0.f;
                if (gk + 1 > gm) va.y = 0.f;
                if (gk + 2 > gm) va.z = 0.f;
                if (gk + 3 > gm) va.w = 0.f;
            }
            As[c4 + 0][r] = va.x;
            As[c4 + 1][r] = va.y;
            As[c4 + 2][r] = va.z;
            As[c4 + 3][r] = va.w;
        }
        // ---- load B tile (BK x BN) ----
#pragma unroll
        for (int i = 0; i < 2; i++) {
            const int idx = tid + i * 256;
            const int r   = idx >> 5;               // 0..15
            const int c4  = (idx & 31) << 2;        // 0..124
            float4 vb = *(const float4*)(B + (size_t)(k0 + r) * ldb + n0 + c4);
            *(float4*)&Bs[r][c4] = vb;
        }
        __syncthreads();

#pragma unroll
        for (int kk = 0; kk < BK; kk++) {
            float ra[8], rb[8];
            *(float4*)&ra[0] = *(const float4*)&As[kk][ty * 8];
            *(float4*)&ra[4] = *(const float4*)&As[kk][ty * 8 + 4];
            *(float4*)&rb[0] = *(const float4*)&Bs[kk][tx * 8];
            *(float4*)&rb[4] = *(const float4*)&Bs[kk][tx * 8 + 4];
#pragma unroll
            for (int i = 0; i < 8; i++)
#pragma unroll
                for (int j = 0; j < 8; j++) acc[i][j] += ra[i] * rb[j];
        }
        __syncthreads();
    }

    // ---- epilogue ----
    const int gmb = m0 + ty * 8;
    const int gnb = n0 + tx * 8;
    if (MODE == 0) {
#pragma unroll
        for (int i = 0; i < 8; i++) {
            const int gm = gmb + i;
            const float b = bias[gm];
            const float* xr = xh_or_pb + (size_t)gm * (2 * DH);   // xh = x[:, 0:DH]
            float* cr = C + (size_t)gm * ldc;
#pragma unroll
            for (int j = 0; j < 8; j++) {
                const int gn = gnb + j;
                cr[gn] = xr[gn] * (acc[i][j] + b);
            }
        }
    } else {
#pragma unroll
        for (int i = 0; i < 8; i++) {
            const int gm = gmb + i;
            float* cr = C + (size_t)gm * ldc;
#pragma unroll
            for (int j = 0; j < 8; j++) {
                const int gn = gnb + j;
                cr[gn] = acc[i][j] + xh_or_pb[gn];
            }
        }
    }
}

// ---------------------------------------------------------------------------
extern "C" void kernel_launch(void* const* d_in, const int* in_sizes, int n_in,
                              void* d_out, int out_size)
{
    const float* x        = (const float*)d_in[0];  // (4096, 4096)
    const float* ln_scale = (const float*)d_in[1];  // (2048,)
    const float* W        = (const float*)d_in[2];  // (4096, 4096)
    const float* sb       = (const float*)d_in[3];  // (4096, 1)
    const float* pw       = (const float*)d_in[4];  // (2048, 1024)
    const float* pb       = (const float*)d_in[5];  // (1024,)
    float* out            = (float*)d_out;          // (4096, 1024)

    float* gnorm = nullptr;
    float* gated = nullptr;
    cudaGetSymbolAddress((void**)&gnorm, g_gate_norm);
    cudaGetSymbolAddress((void**)&gated, g_gated);

    // 1) LayerNorm of gate half
    ln_kernel<<<SEQ, 256>>>(x, ln_scale);

    // 2) Causal spatial mixing + bias + gating multiply by xh
    {
        dim3 grid(DH / BN, SEQ / BM);   // (16, 32)
        gemm_kernel<0><<<grid, 256>>>(W, gnorm, gated, x, sb);
    }

    // 3) Output projection + bias
    {
        dim3 grid(DOUT / BN, SEQ / BM); // (8, 32)
        gemm_kernel<1><<<grid, 256>>>(gated, pw, out, pb, nullptr);
    }
}

// round 4
// speedup vs baseline: 4.0215x; 4.0215x over previous
#include <cuda_runtime.h>
#include <cuda_bf16.h>

#define SEQ   4096
#define DH    2048
#define DOUT  1024
#define LN_EPS 1e-5f

// ---------------------------------------------------------------------------
// Scratch (__device__ globals; allocation-free rule)
// ---------------------------------------------------------------------------
__device__ __nv_bfloat16 g_ln [(size_t)SEQ * DH];    // LN(gate) [n][d]
__device__ __nv_bfloat16 g_Ahi[(size_t)SEQ * DH];    // gated hi [m][d]
__device__ __nv_bfloat16 g_Alo[(size_t)SEQ * DH];    // gated lo [m][d]
__device__ __nv_bfloat16 g_Bhi[(size_t)DH * DOUT];   // proj_w hi [d][j]
__device__ __nv_bfloat16 g_Blo[(size_t)DH * DOUT];   // proj_w lo [d][j]

// ---------------------------------------------------------------------------
// PTX helpers (compute_103-legal: ldmatrix / mma.sync / cp.async)
// ---------------------------------------------------------------------------
__device__ __forceinline__ unsigned smem_u32(const void* p) {
    unsigned a;
    asm("{ .reg .u64 t; cvta.to.shared.u64 t, %1; cvt.u32.u64 %0, t; }"
        : "=r"(a) : "l"(p));
    return a;
}

__device__ __forceinline__ void ldsm_x4(unsigned* r, unsigned addr) {
    asm volatile("ldmatrix.sync.aligned.m8n8.x4.shared.b16 {%0,%1,%2,%3}, [%4];"
                 : "=r"(r[0]), "=r"(r[1]), "=r"(r[2]), "=r"(r[3]) : "r"(addr));
}
__device__ __forceinline__ void ldsm_x4_t(unsigned* r, unsigned addr) {
    asm volatile("ldmatrix.sync.aligned.m8n8.x4.trans.shared.b16 {%0,%1,%2,%3}, [%4];"
                 : "=r"(r[0]), "=r"(r[1]), "=r"(r[2]), "=r"(r[3]) : "r"(addr));
}

__device__ __forceinline__ void mma16816(float* c, const unsigned* a,
                                         unsigned b0, unsigned b1) {
    asm volatile(
        "mma.sync.aligned.m16n8k16.row.col.f32.bf16.bf16.f32 "
        "{%0,%1,%2,%3}, {%4,%5,%6,%7}, {%8,%9}, {%0,%1,%2,%3};"
        : "+f"(c[0]), "+f"(c[1]), "+f"(c[2]), "+f"(c[3])
        : "r"(a[0]), "r"(a[1]), "r"(a[2]), "r"(a[3]), "r"(b0), "r"(b1));
}

__device__ __forceinline__ void cp16(unsigned dst, const void* src) {
    asm volatile("cp.async.cg.shared.global [%0], [%1], 16;"
                 :: "r"(dst), "l"(src) : "memory");
}
__device__ __forceinline__ void cp_commit() {
    asm volatile("cp.async.commit_group;" ::: "memory");
}
template <int N>
__device__ __forceinline__ void cp_wait() {
    asm volatile("cp.async.wait_group %0;" :: "n"(N) : "memory");
}

__device__ __forceinline__ unsigned pack2(float a, float b) {
    __nv_bfloat162 h = __floats2bfloat162_rn(a, b);
    return *reinterpret_cast<unsigned*>(&h);
}

// smem padded strides (bf16 elems) — both chosen conflict-free for ldmatrix
static constexpr int AS_STR = 40;    // [128][40]  (A tiles, k-major rows)
static constexpr int BS_STR = 136;   // [32][136]  (B tiles, [k][n] rows)
static constexpr int AS_BUF = 128 * AS_STR;   // 5120 elems / buffer
static constexpr int BS_BUF = 32 * BS_STR;    // 4352 elems / buffer

// ---------------------------------------------------------------------------
// Kernel 1: LayerNorm (scale only) of gate half -> bf16 g_ln[n][d]
// ---------------------------------------------------------------------------
__global__ __launch_bounds__(256) void ln_kernel(const float* __restrict__ x,
                                                 const float* __restrict__ ln_scale)
{
    const int row = blockIdx.x;
    const int t   = threadIdx.x;
    const float* g = x + (size_t)row * (2 * DH) + DH;

    float v[8];
    float sum = 0.f, sumsq = 0.f;
#pragma unroll
    for (int i = 0; i < 8; i++) {
        float val = g[t + i * 256];
        v[i] = val; sum += val; sumsq += val * val;
    }
    __shared__ float s1[8], s2[8];
#pragma unroll
    for (int o = 16; o > 0; o >>= 1) {
        sum   += __shfl_xor_sync(0xFFFFFFFFu, sum, o);
        sumsq += __shfl_xor_sync(0xFFFFFFFFu, sumsq, o);
    }
    const int w = t >> 5, l = t & 31;
    if (l == 0) { s1[w] = sum; s2[w] = sumsq; }
    __syncthreads();
    if (w == 0) {
        sum   = (l < 8) ? s1[l] : 0.f;
        sumsq = (l < 8) ? s2[l] : 0.f;
#pragma unroll
        for (int o = 4; o > 0; o >>= 1) {
            sum   += __shfl_xor_sync(0xFFFFFFFFu, sum, o);
            sumsq += __shfl_xor_sync(0xFFFFFFFFu, sumsq, o);
        }
        if (l == 0) { s1[0] = sum; s2[0] = sumsq; }
    }
    __syncthreads();
    const float mean = s1[0] * (1.0f / DH);
    const float var  = s2[0] * (1.0f / DH) - mean * mean;
    const float inv  = rsqrtf(var + LN_EPS);
#pragma unroll
    for (int i = 0; i < 8; i++) {
        const int j = t + i * 256;
        g_ln[(size_t)row * DH + j] =
            __float2bfloat16_rn((v[i] - mean) * inv * ln_scale[j]);
    }
}

// ---------------------------------------------------------------------------
// Kernel 2: split proj_w fp32 [d][j] -> hi/lo bf16 (same layout)
// ---------------------------------------------------------------------------
__global__ __launch_bounds__(256) void split_pw_kernel(const float* __restrict__ pw)
{
    const size_t i = ((size_t)blockIdx.x * 256 + threadIdx.x) * 4;
    float4 v = *(const float4*)(pw + i);
    __nv_bfloat16 h0 = __float2bfloat16_rn(v.x);
    __nv_bfloat16 h1 = __float2bfloat16_rn(v.y);
    __nv_bfloat16 h2 = __float2bfloat16_rn(v.z);
    __nv_bfloat16 h3 = __float2bfloat16_rn(v.w);
    uint2 hi = make_uint2(pack2(__bfloat162float(h0), 0.f), 0);
    // pack hi pair-wise preserving order
    hi.x = pack2(v.x, v.y); hi.y = pack2(v.z, v.w);   // rn-rounded hi parts
    uint2 lo;
    lo.x = pack2(v.x - __bfloat162float(h0), v.y - __bfloat162float(h1));
    lo.y = pack2(v.z - __bfloat162float(h2), v.w - __bfloat162float(h3));
    *(uint2*)(g_Bhi + i) = hi;
    *(uint2*)(g_Blo + i) = lo;
}

// ---------------------------------------------------------------------------
// Kernel 3: spatial mixing (HMMA bf16). BM=128 BN=128 BK=32, 256 thr.
// C[m][d] = sum_{n<=m} W[m][n]*g_ln[n][d]; epi: v = xh*(C+sb[m]) -> Ahi/Alo
// ---------------------------------------------------------------------------
__global__ __launch_bounds__(256) void spatial_kernel(const float* __restrict__ W,
                                                      const float* __restrict__ x,
                                                      const float* __restrict__ sb)
{
    extern __shared__ __nv_bfloat16 sm[];
    __nv_bfloat16* As = sm;                 // [2][128][40]
    __nv_bfloat16* Bs = sm + 2 * AS_BUF;    // [2][32][136]

    const int tid  = threadIdx.x;
    const int lane = tid & 31;
    const int wid  = tid >> 5;
    const int ntile = blockIdx.x & 15;
    const int mtile = 31 - (blockIdx.x >> 4);   // heavy tiles first
    const int m0 = mtile * 128;
    const int n0 = ntile * 128;
    const int wm = wid & 3;      // 4 warps along M (32 rows each)
    const int wn = wid >> 2;     // 2 warps along N (64 cols each)

    float acc[2][8][4];
#pragma unroll
    for (int i = 0; i < 2; i++)
#pragma unroll
        for (int j = 0; j < 8; j++)
#pragma unroll
            for (int q = 0; q < 4; q++) acc[i][j][q] = 0.f;

    const int r_a  = tid >> 1;           // A: row per thread
    const int cb_a = (tid & 1) * 16;     // A: col base (16 floats)

    auto ldgA = [&](int k0, float4* f) {
        const float* src = W + (size_t)(m0 + r_a) * SEQ + k0 + cb_a;
        f[0] = *(const float4*)(src + 0);
        f[1] = *(const float4*)(src + 4);
        f[2] = *(const float4*)(src + 8);
        f[3] = *(const float4*)(src + 12);
    };
    auto stsA = [&](int buf, int k0, float4* f) {
        const int gm = m0 + r_a;
        if (k0 >= m0) {                       // tril mask possible
#pragma unroll
            for (int j = 0; j < 4; j++) {
                float* e = (float*)&f[j];
#pragma unroll
                for (int q = 0; q < 4; q++)
                    if (k0 + cb_a + j * 4 + q > gm) e[q] = 0.f;
            }
        }
        uint4 p0 = make_uint4(pack2(f[0].x, f[0].y), pack2(f[0].z, f[0].w),
                              pack2(f[1].x, f[1].y), pack2(f[1].z, f[1].w));
        uint4 p1 = make_uint4(pack2(f[2].x, f[2].y), pack2(f[2].z, f[2].w),
                              pack2(f[3].x, f[3].y), pack2(f[3].z, f[3].w));
        __nv_bfloat16* dst = As + buf * AS_BUF + r_a * AS_STR + cb_a;
        *(uint4*)(dst + 0) = p0;
        *(uint4*)(dst + 8) = p1;
    };
    auto cpB = [&](int buf, int k0) {
#pragma unroll
        for (int it = 0; it < 2; it++) {
            const int idx = tid + it * 256;
            const int r   = idx >> 4;            // 0..31 (k)
            const int c8  = (idx & 15) * 8;      // 0..120 (n)
            cp16(smem_u32(Bs + buf * BS_BUF + r * BS_STR + c8),
                 g_ln + (size_t)(k0 + r) * DH + n0 + c8);
        }
    };
    auto compute = [&](int buf) {
        const __nv_bfloat16* A0 = As + buf * AS_BUF;
        const __nv_bfloat16* B0 = Bs + buf * BS_BUF;
#pragma unroll
        for (int ks = 0; ks < 2; ks++) {
            unsigned a[2][4], b[4][4];
#pragma unroll
            for (int am = 0; am < 2; am++)
                ldsm_x4(a[am], smem_u32(A0 + (wm * 32 + am * 16 + (lane & 15)) * AS_STR
                                           + ks * 16 + (lane >> 4) * 8));
#pragma unroll
            for (int p = 0; p < 4; p++)
                ldsm_x4_t(b[p], smem_u32(B0 + (ks * 16 + (lane & 15)) * BS_STR
                                            + wn * 64 + p * 16 + (lane >> 4) * 8));
#pragma unroll
            for (int am = 0; am < 2; am++)
#pragma unroll
                for (int p = 0; p < 4; p++) {
                    mma16816(acc[am][2 * p + 0], a[am], b[p][0], b[p][1]);
                    mma16816(acc[am][2 * p + 1], a[am], b[p][2], b[p][3]);
                }
        }
    };

    const int nch = 4 * mtile + 4;       // kend = m0+128
    float4 fr[4];
    ldgA(0, fr);
    stsA(0, 0, fr);
    cpB(0, 0); cp_commit();
    cp_wait<0>();
    __syncthreads();

    for (int i = 0; i < nch; i++) {
        const int buf = i & 1;
        const bool more = (i + 1 < nch);
        if (more) {
            ldgA((i + 1) * 32, fr);
            cpB(buf ^ 1, (i + 1) * 32); cp_commit();
        }
        compute(buf);
        if (more) {
            stsA(buf ^ 1, (i + 1) * 32, fr);
            cp_wait<0>();
        }
        __syncthreads();
    }

    // epilogue: gated = xh * (acc + sb[m]); split hi/lo, store bf16
#pragma unroll
    for (int am = 0; am < 2; am++) {
        const int gmb = m0 + wm * 32 + am * 16 + (lane >> 2);
#pragma unroll
        for (int bn = 0; bn < 8; bn++) {
            const int gc = n0 + wn * 64 + bn * 8 + (lane & 3) * 2;
#pragma unroll
            for (int half = 0; half < 2; half++) {
                const int gm = gmb + half * 8;
                const float bias = sb[gm];
                const float2 xv = *(const float2*)(x + (size_t)gm * SEQ + gc);
                float v0 = xv.x * (acc[am][bn][half * 2 + 0] + bias);
                float v1 = xv.y * (acc[am][bn][half * 2 + 1] + bias);
                __nv_bfloat16 h0 = __float2bfloat16_rn(v0);
                __nv_bfloat16 h1 = __float2bfloat16_rn(v1);
                *(unsigned*)(g_Ahi + (size_t)gm * DH + gc) =
                    pack2(v0, v1);
                *(unsigned*)(g_Alo + (size_t)gm * DH + gc) =
                    pack2(v0 - __bfloat162float(h0), v1 - __bfloat162float(h1));
            }
        }
    }
}

// ---------------------------------------------------------------------------
// Kernel 4: projection (HMMA bf16 split, 3 passes). BM=128 BN=128 BK=32.
// out = Ahi@Bhi + Alo@Bhi + Ahi@Blo + pb
// ---------------------------------------------------------------------------
__global__ __launch_bounds__(256) void proj_kernel(const float* __restrict__ pb,
                                                   float* __restrict__ out)
{
    extern __shared__ __nv_bfloat16 sm[];
    __nv_bfloat16* Ah = sm;                                 // [2][128][40]
    __nv_bfloat16* Al = sm + 2 * AS_BUF;                    // [2][128][40]
    __nv_bfloat16* Bh = sm + 4 * AS_BUF;                    // [2][32][136]
    __nv_bfloat16* Bl = sm + 4 * AS_BUF + 2 * BS_BUF;       // [2][32][136]

    const int tid  = threadIdx.x;
    const int lane = tid & 31;
    const int wid  = tid >> 5;
    const int ntile = blockIdx.x & 7;
    const int mtile = blockIdx.x >> 3;
    const int m0 = mtile * 128;
    const int n0 = ntile * 128;
    const int wm = wid & 3;
    const int wn = wid >> 2;

    float acc[2][8][4];
#pragma unroll
    for (int i = 0; i < 2; i++)
#pragma unroll
        for (int j = 0; j < 8; j++)
#pragma unroll
            for (int q = 0; q < 4; q++) acc[i][j][q] = 0.f;

    auto cpStage = [&](int buf, int k0) {
#pragma unroll
        for (int it = 0; it < 2; it++) {
            const int idx = tid + it * 256;
            {   // A tiles [128][32]
                const int r  = idx >> 2;
                const int c8 = (idx & 3) * 8;
                const size_t src = (size_t)(m0 + r) * DH + k0 + c8;
                const unsigned off = buf * AS_BUF + r * AS_STR + c8;
                cp16(smem_u32(Ah + off), g_Ahi + src);
                cp16(smem_u32(Al + off), g_Alo + src);
            }
            {   // B tiles [32][128]
                const int r  = idx >> 4;
                const int c8 = (idx & 15) * 8;
                const size_t src = (size_t)(k0 + r) * DOUT + n0 + c8;
                const unsigned off = buf * BS_BUF + r * BS_STR + c8;
                cp16(smem_u32(Bh + off), g_Bhi + src);
                cp16(smem_u32(Bl + off), g_Blo + src);
            }
        }
    };
    auto compute = [&](int buf) {
        const __nv_bfloat16* A0h = Ah + buf * AS_BUF;
        const __nv_bfloat16* A0l = Al + buf * AS_BUF;
        const __nv_bfloat16* B0h = Bh + buf * BS_BUF;
        const __nv_bfloat16* B0l = Bl + buf * BS_BUF;
#pragma unroll
        for (int ks = 0; ks < 2; ks++) {
            unsigned ah[2][4], al[2][4], bh[4][4], bl[4][4];
#pragma unroll
            for (int am = 0; am < 2; am++) {
                const unsigned o = (wm * 32 + am * 16 + (lane & 15)) * AS_STR
                                 + ks * 16 + (lane >> 4) * 8;
                ldsm_x4(ah[am], smem_u32(A0h + o));
                ldsm_x4(al[am], smem_u32(A0l + o));
            }
#pragma unroll
            for (int p = 0; p < 4; p++) {
                const unsigned o = (ks * 16 + (lane & 15)) * BS_STR
                                 + wn * 64 + p * 16 + (lane >> 4) * 8;
                ldsm_x4_t(bh[p], smem_u32(B0h + o));
                ldsm_x4_t(bl[p], smem_u32(B0l + o));
            }
#pragma unroll
            for (int am = 0; am < 2; am++)
#pragma unroll
                for (int p = 0; p < 4; p++) {
                    mma16816(acc[am][2 * p + 0], ah[am], bh[p][0], bh[p][1]);
                    mma16816(acc[am][2 * p + 1], ah[am], bh[p][2], bh[p][3]);
                    mma16816(acc[am][2 * p + 0], al[am], bh[p][0], bh[p][1]);
                    mma16816(acc[am][2 * p + 1], al[am], bh[p][2], bh[p][3]);
                    mma16816(acc[am][2 * p + 0], ah[am], bl[p][0], bl[p][1]);
                    mma16816(acc[am][2 * p + 1], ah[am], bl[p][2], bl[p][3]);
                }
        }
    };

    const int nch = DH / 32;   // 64
    cpStage(0, 0); cp_commit();
    cp_wait<0>();
    __syncthreads();

    for (int i = 0; i < nch; i++) {
        const int buf = i & 1;
        const bool more = (i + 1 < nch);
        if (more) { cpStage(buf ^ 1, (i + 1) * 32); cp_commit(); }
        compute(buf);
        if (more) cp_wait<0>();
        __syncthreads();
    }

    // epilogue: + pb, fp32 stores
#pragma unroll
    for (int am = 0; am < 2; am++) {
        const int gmb = m0 + wm * 32 + am * 16 + (lane >> 2);
#pragma unroll
        for (int bn = 0; bn < 8; bn++) {
            const int gc = n0 + wn * 64 + bn * 8 + (lane & 3) * 2;
            const float2 bias = *(const float2*)(pb + gc);
#pragma unroll
            for (int half = 0; half < 2; half++) {
                const int gm = gmb + half * 8;
                float2 o;
                o.x = acc[am][bn][half * 2 + 0] + bias.x;
                o.y = acc[am][bn][half * 2 + 1] + bias.y;
                *(float2*)(out + (size_t)gm * DOUT + gc) = o;
            }
        }
    }
}

// ---------------------------------------------------------------------------
extern "C" void kernel_launch(void* const* d_in, const int* in_sizes, int n_in,
                              void* d_out, int out_size)
{
    const float* x        = (const float*)d_in[0];  // (4096, 4096)
    const float* ln_scale = (const float*)d_in[1];  // (2048,)
    const float* W        = (const float*)d_in[2];  // (4096, 4096)
    const float* sb       = (const float*)d_in[3];  // (4096, 1)
    const float* pw       = (const float*)d_in[4];  // (2048, 1024)
    const float* pb       = (const float*)d_in[5];  // (1024,)
    float* out            = (float*)d_out;          // (4096, 1024)

    const int SP_SMEM = (2 * AS_BUF + 2 * BS_BUF) * 2;              // 37888 B
    const int PJ_SMEM = (4 * AS_BUF + 4 * BS_BUF) * 2;              // 75776 B
    static bool attr_done = false;
    cudaFuncSetAttribute(proj_kernel,
                         cudaFuncAttributeMaxDynamicSharedMemorySize, PJ_SMEM);
    (void)attr_done;

    ln_kernel<<<SEQ, 256>>>(x, ln_scale);
    split_pw_kernel<<<(DH * DOUT) / (256 * 4), 256>>>(pw);
    spatial_kernel<<<512, 256, SP_SMEM>>>(W, x, sb);
    proj_kernel<<<256, 256, PJ_SMEM>>>(pb, out);
}

// round 6
// speedup vs baseline: 5.2059x; 1.2945x over previous
#include <cuda_runtime.h>
#include <cuda_bf16.h>

#define SEQ   4096
#define DH    2048
#define DOUT  1024
#define LN_EPS 1e-5f

// ---------------------------------------------------------------------------
// Scratch (__device__ globals; allocation-free rule)
// ---------------------------------------------------------------------------
__device__ __nv_bfloat16 g_ln   [(size_t)SEQ * DH];   // LN(gate) bf16 [n][d]
__device__ float         g_gated[(size_t)SEQ * DH];   // gated, tf32-rounded [m][d]
__device__ float         g_pwt  [(size_t)DH * DOUT];  // proj_w, tf32-rounded [d][j]

// ---------------------------------------------------------------------------
// PTX helpers (compute_103-legal: ldmatrix / mma.sync / cp.async)
// ---------------------------------------------------------------------------
__device__ __forceinline__ unsigned smem_u32(const void* p) {
    unsigned a;
    asm("{ .reg .u64 t; cvta.to.shared.u64 t, %1; cvt.u32.u64 %0, t; }"
        : "=r"(a) : "l"(p));
    return a;
}

__device__ __forceinline__ void ldsm_x4(unsigned* r, unsigned addr) {
    asm volatile("ldmatrix.sync.aligned.m8n8.x4.shared.b16 {%0,%1,%2,%3}, [%4];"
                 : "=r"(r[0]), "=r"(r[1]), "=r"(r[2]), "=r"(r[3]) : "r"(addr));
}
__device__ __forceinline__ void ldsm_x4_t(unsigned* r, unsigned addr) {
    asm volatile("ldmatrix.sync.aligned.m8n8.x4.trans.shared.b16 {%0,%1,%2,%3}, [%4];"
                 : "=r"(r[0]), "=r"(r[1]), "=r"(r[2]), "=r"(r[3]) : "r"(addr));
}

__device__ __forceinline__ void mma16816(float* c, const unsigned* a,
                                         unsigned b0, unsigned b1) {
    asm volatile(
        "mma.sync.aligned.m16n8k16.row.col.f32.bf16.bf16.f32 "
        "{%0,%1,%2,%3}, {%4,%5,%6,%7}, {%8,%9}, {%0,%1,%2,%3};"
        : "+f"(c[0]), "+f"(c[1]), "+f"(c[2]), "+f"(c[3])
        : "r"(a[0]), "r"(a[1]), "r"(a[2]), "r"(a[3]), "r"(b0), "r"(b1));
}

__device__ __forceinline__ void mma1688_tf32(float* c, const unsigned* a,
                                             unsigned b0, unsigned b1) {
    asm volatile(
        "mma.sync.aligned.m16n8k8.row.col.f32.tf32.tf32.f32 "
        "{%0,%1,%2,%3}, {%4,%5,%6,%7}, {%8,%9}, {%0,%1,%2,%3};"
        : "+f"(c[0]), "+f"(c[1]), "+f"(c[2]), "+f"(c[3])
        : "r"(a[0]), "r"(a[1]), "r"(a[2]), "r"(a[3]), "r"(b0), "r"(b1));
}

__device__ __forceinline__ void cp16(unsigned dst, const void* src) {
    asm volatile("cp.async.cg.shared.global [%0], [%1], 16;"
                 :: "r"(dst), "l"(src) : "memory");
}
__device__ __forceinline__ void cp_commit() {
    asm volatile("cp.async.commit_group;" ::: "memory");
}
template <int N>
__device__ __forceinline__ void cp_wait() {
    asm volatile("cp.async.wait_group %0;" :: "n"(N) : "memory");
}

__device__ __forceinline__ unsigned pack2(float a, float b) {
    __nv_bfloat162 h = __floats2bfloat162_rn(a, b);
    return *reinterpret_cast<unsigned*>(&h);
}
__device__ __forceinline__ unsigned to_tf32(float f) {
    unsigned u;
    asm("cvt.rna.tf32.f32 %0, %1;" : "=r"(u) : "f"(f));
    return u;
}

// spatial smem strides (bf16 elems), conflict-free for ldmatrix
static constexpr int SP_AS_STR = 40;    // [128][40]
static constexpr int SP_BS_STR = 264;   // [32][264]  (BN=256 + 8 pad)
static constexpr int SP_AS_BUF = 128 * SP_AS_STR;
static constexpr int SP_BS_BUF = 32 * SP_BS_STR;

// proj smem strides (fp32 elems), conflict-free for LDS.32 fragment loads
static constexpr int PJ_AS_STR = 36;    // [128][36]
static constexpr int PJ_BS_STR = 136;   // [32][136]
static constexpr int PJ_AS_BUF = 128 * PJ_AS_STR;
static constexpr int PJ_BS_BUF = 32 * PJ_BS_STR;

// ---------------------------------------------------------------------------
// Kernel 1: LayerNorm (scale only) of gate half -> bf16 g_ln[n][d]
// ---------------------------------------------------------------------------
__global__ __launch_bounds__(256) void ln_kernel(const float* __restrict__ x,
                                                 const float* __restrict__ ln_scale)
{
    const int row = blockIdx.x;
    const int t   = threadIdx.x;
    const float* g = x + (size_t)row * (2 * DH) + DH;

    float v[8];
    float sum = 0.f, sumsq = 0.f;
#pragma unroll
    for (int i = 0; i < 8; i++) {
        float val = g[t + i * 256];
        v[i] = val; sum += val; sumsq += val * val;
    }
    __shared__ float s1[8], s2[8];
#pragma unroll
    for (int o = 16; o > 0; o >>= 1) {
        sum   += __shfl_xor_sync(0xFFFFFFFFu, sum, o);
        sumsq += __shfl_xor_sync(0xFFFFFFFFu, sumsq, o);
    }
    const int w = t >> 5, l = t & 31;
    if (l == 0) { s1[w] = sum; s2[w] = sumsq; }
    __syncthreads();
    if (w == 0) {
        sum   = (l < 8) ? s1[l] : 0.f;
        sumsq = (l < 8) ? s2[l] : 0.f;
#pragma unroll
        for (int o = 4; o > 0; o >>= 1) {
            sum   += __shfl_xor_sync(0xFFFFFFFFu, sum, o);
            sumsq += __shfl_xor_sync(0xFFFFFFFFu, sumsq, o);
        }
        if (l == 0) { s1[0] = sum; s2[0] = sumsq; }
    }
    __syncthreads();
    const float mean = s1[0] * (1.0f / DH);
    const float var  = s2[0] * (1.0f / DH) - mean * mean;
    const float inv  = rsqrtf(var + LN_EPS);
#pragma unroll
    for (int i = 0; i < 8; i++) {
        const int j = t + i * 256;
        g_ln[(size_t)row * DH + j] =
            __float2bfloat16_rn((v[i] - mean) * inv * ln_scale[j]);
    }
}

// ---------------------------------------------------------------------------
// Kernel 2: round proj_w to tf32 (same [d][j] layout)
// ---------------------------------------------------------------------------
__global__ __launch_bounds__(256) void pw_cvt_kernel(const float* __restrict__ pw)
{
    const size_t i = ((size_t)blockIdx.x * 256 + threadIdx.x) * 4;
    float4 v = *(const float4*)(pw + i);
    uint4 u = make_uint4(to_tf32(v.x), to_tf32(v.y), to_tf32(v.z), to_tf32(v.w));
    *(uint4*)(g_pwt + i) = u;
}

// ---------------------------------------------------------------------------
// Kernel 3: spatial mixing (HMMA bf16). BM=128 BN=256 BK=32, 512 thr.
// C[m][d] = sum_{n<=m} W[m][n]*g_ln[n][d]; epi: g_gated = tf32(xh*(C+sb[m]))
// ---------------------------------------------------------------------------
__global__ __launch_bounds__(512) void spatial_kernel(const float* __restrict__ W,
                                                      const float* __restrict__ x,
                                                      const float* __restrict__ sb)
{
    extern __shared__ __nv_bfloat16 sm[];
    __nv_bfloat16* As = sm;                    // [2][128][40]
    __nv_bfloat16* Bs = sm + 2 * SP_AS_BUF;    // [2][32][264]

    const int tid  = threadIdx.x;
    const int lane = tid & 31;
    const int wid  = tid >> 5;
    const int ntile = blockIdx.x & 7;
    const int mtile = 31 - (blockIdx.x >> 3);   // heavy tiles first
    const int m0 = mtile * 128;
    const int n0 = ntile * 256;
    const int wm = wid & 3;      // 4 warps along M (32 rows)
    const int wn = wid >> 2;     // 4 warps along N (64 cols)

    float acc[2][8][4];
#pragma unroll
    for (int i = 0; i < 2; i++)
#pragma unroll
        for (int j = 0; j < 8; j++)
#pragma unroll
            for (int q = 0; q < 4; q++) acc[i][j][q] = 0.f;

    // A staging: ONE float4-pair per thread (512 thr x 8 floats = 128x32 tile)
    const int ra0 = tid >> 2;            // 0..127
    const int ca0 = (tid & 3) * 8;       // 0,8,16,24

    float4 fr[2];
    auto ldgA = [&](int k0) {
        const float* s0 = W + (size_t)(m0 + ra0) * SEQ + k0 + ca0;
        fr[0] = *(const float4*)(s0 + 0);
        fr[1] = *(const float4*)(s0 + 4);
    };
    auto stsA = [&](int buf, int k0) {
        if (k0 >= m0) {   // tril mask possible (diagonal block)
            const int gm = m0 + ra0;
#pragma unroll
            for (int j = 0; j < 2; j++) {
                const int cb = ca0 + j * 4;
                float* e = (float*)&fr[j];
#pragma unroll
                for (int q = 0; q < 4; q++)
                    if (k0 + cb + q > gm) e[q] = 0.f;
            }
        }
        __nv_bfloat16* d0 = As + buf * SP_AS_BUF + ra0 * SP_AS_STR + ca0;
        *(uint4*)d0 = make_uint4(pack2(fr[0].x, fr[0].y), pack2(fr[0].z, fr[0].w),
                                 pack2(fr[1].x, fr[1].y), pack2(fr[1].z, fr[1].w));
    };
    auto cpB = [&](int buf, int k0) {
#pragma unroll
        for (int it = 0; it < 2; it++) {
            const int idx = tid + it * 512;
            const int r   = idx >> 5;            // 0..31 (k)
            const int c8  = (idx & 31) * 8;      // 0..248 (n)
            cp16(smem_u32(Bs + buf * SP_BS_BUF + r * SP_BS_STR + c8),
                 g_ln + (size_t)(k0 + r) * DH + n0 + c8);
        }
    };
    auto compute = [&](int buf) {
        const __nv_bfloat16* A0 = As + buf * SP_AS_BUF;
        const __nv_bfloat16* B0 = Bs + buf * SP_BS_BUF;
#pragma unroll
        for (int ks = 0; ks < 2; ks++) {
            unsigned a[2][4], b[4][4];
#pragma unroll
            for (int am = 0; am < 2; am++)
                ldsm_x4(a[am], smem_u32(A0 + (wm * 32 + am * 16 + (lane & 15)) * SP_AS_STR
                                           + ks * 16 + (lane >> 4) * 8));
#pragma unroll
            for (int p = 0; p < 4; p++)
                ldsm_x4_t(b[p], smem_u32(B0 + (ks * 16 + (lane & 15)) * SP_BS_STR
                                            + wn * 64 + p * 16 + (lane >> 4) * 8));
#pragma unroll
            for (int am = 0; am < 2; am++)
#pragma unroll
                for (int p = 0; p < 4; p++) {
                    mma16816(acc[am][2 * p + 0], a[am], b[p][0], b[p][1]);
                    mma16816(acc[am][2 * p + 1], a[am], b[p][2], b[p][3]);
                }
        }
    };

    const int nch = 4 * mtile + 4;       // kend = m0+128
    ldgA(0);
    stsA(0, 0);
    cpB(0, 0); cp_commit();
    cp_wait<0>();
    __syncthreads();

    for (int i = 0; i < nch; i++) {
        const int buf = i & 1;
        const bool more = (i + 1 < nch);
        if (more) {
            ldgA((i + 1) * 32);
            cpB(buf ^ 1, (i + 1) * 32); cp_commit();
        }
        compute(buf);
        if (more) {
            stsA(buf ^ 1, (i + 1) * 32);
            cp_wait<0>();
        }
        __syncthreads();
    }

    // epilogue: g_gated = tf32( xh * (acc + sb[m]) )
#pragma unroll
    for (int am = 0; am < 2; am++) {
        const int gmb = m0 + wm * 32 + am * 16 + (lane >> 2);
#pragma unroll
        for (int nb = 0; nb < 8; nb++) {
            const int gc = n0 + wn * 64 + nb * 8 + (lane & 3) * 2;
#pragma unroll
            for (int half = 0; half < 2; half++) {
                const int gm = gmb + half * 8;
                const float bias = sb[gm];
                const float2 xv = *(const float2*)(x + (size_t)gm * SEQ + gc);
                float v0 = xv.x * (acc[am][nb][half * 2 + 0] + bias);
                float v1 = xv.y * (acc[am][nb][half * 2 + 1] + bias);
                *(uint2*)(g_gated + (size_t)gm * DH + gc) =
                    make_uint2(to_tf32(v0), to_tf32(v1));
            }
        }
    }
}

// ---------------------------------------------------------------------------
// Kernel 4: projection (tf32 m16n8k8, single pass). BM=128 BN=128 BK=32.
// out = g_gated @ g_pwt + pb
// ---------------------------------------------------------------------------
__global__ __launch_bounds__(256, 2) void proj_kernel(const float* __restrict__ pb,
                                                      float* __restrict__ out)
{
    extern __shared__ float smf[];
    float* Af = smf;                  // [2][128][36]
    float* Bf = smf + 2 * PJ_AS_BUF;  // [2][32][136]

    const int tid  = threadIdx.x;
    const int lane = tid & 31;
    const int wid  = tid >> 5;
    const int ntile = blockIdx.x & 7;
    const int mtile = blockIdx.x >> 3;
    const int m0 = mtile * 128;
    const int n0 = ntile * 128;
    const int wm = wid & 3;      // 4 warps M (32 rows)
    const int wn = wid >> 2;     // 2 warps N (64 cols)
    const int g = lane >> 2;     // groupID 0..7
    const int t = lane & 3;      // thread-in-group

    float acc[2][8][4];
#pragma unroll
    for (int i = 0; i < 2; i++)
#pragma unroll
        for (int j = 0; j < 8; j++)
#pragma unroll
            for (int q = 0; q < 4; q++) acc[i][j][q] = 0.f;

    auto cpStage = [&](int buf, int k0) {
#pragma unroll
        for (int it = 0; it < 4; it++) {
            const int idx = tid + it * 256;
            {   // A tile [128][32] fp32
                const int r = idx >> 3;
                const int c = (idx & 7) * 4;
                cp16(smem_u32(Af + buf * PJ_AS_BUF + r * PJ_AS_STR + c),
                     g_gated + (size_t)(m0 + r) * DH + k0 + c);
            }
            {   // B tile [32][128] fp32
                const int r = idx >> 5;
                const int c = (idx & 31) * 4;
                cp16(smem_u32(Bf + buf * PJ_BS_BUF + r * PJ_BS_STR + c),
                     g_pwt + (size_t)(k0 + r) * DOUT + n0 + c);
            }
        }
    };
    auto compute = [&](int buf) {
        const float* A0 = Af + buf * PJ_AS_BUF;
        const float* B0 = Bf + buf * PJ_BS_BUF;
#pragma unroll
        for (int ks = 0; ks < 4; ks++) {
            unsigned a[2][4], b[8][2];
#pragma unroll
            for (int mb = 0; mb < 2; mb++) {
                const float* Ap = A0 + (wm * 32 + mb * 16) * PJ_AS_STR + ks * 8;
                a[mb][0] = __float_as_uint(Ap[(g    ) * PJ_AS_STR + t    ]);
                a[mb][1] = __float_as_uint(Ap[(g + 8) * PJ_AS_STR + t    ]);
                a[mb][2] = __float_as_uint(Ap[(g    ) * PJ_AS_STR + t + 4]);
                a[mb][3] = __float_as_uint(Ap[(g + 8) * PJ_AS_STR + t + 4]);
            }
#pragma unroll
            for (int nb = 0; nb < 8; nb++) {
                const float* Bp = B0 + ks * 8 * PJ_BS_STR + wn * 64 + nb * 8 + g;
                b[nb][0] = __float_as_uint(Bp[ t      * PJ_BS_STR]);
                b[nb][1] = __float_as_uint(Bp[(t + 4) * PJ_BS_STR]);
            }
#pragma unroll
            for (int mb = 0; mb < 2; mb++)
#pragma unroll
                for (int nb = 0; nb < 8; nb++)
                    mma1688_tf32(acc[mb][nb], a[mb], b[nb][0], b[nb][1]);
        }
    };

    const int nch = DH / 32;   // 64
    cpStage(0, 0); cp_commit();
    cp_wait<0>();
    __syncthreads();

    for (int i = 0; i < nch; i++) {
        const int buf = i & 1;
        const bool more = (i + 1 < nch);
        if (more) { cpStage(buf ^ 1, (i + 1) * 32); cp_commit(); }
        compute(buf);
        if (more) cp_wait<0>();
        __syncthreads();
    }

    // epilogue: + pb
#pragma unroll
    for (int mb = 0; mb < 2; mb++) {
        const int gmb = m0 + wm * 32 + mb * 16 + g;
#pragma unroll
        for (int nb = 0; nb < 8; nb++) {
            const int gc = n0 + wn * 64 + nb * 8 + t * 2;
            const float2 bias = *(const float2*)(pb + gc);
#pragma unroll
            for (int half = 0; half < 2; half++) {
                const int gm = gmb + half * 8;
                float2 o;
                o.x = acc[mb][nb][half * 2 + 0] + bias.x;
                o.y = acc[mb][nb][half * 2 + 1] + bias.y;
                *(float2*)(out + (size_t)gm * DOUT + gc) = o;
            }
        }
    }
}

// ---------------------------------------------------------------------------
extern "C" void kernel_launch(void* const* d_in, const int* in_sizes, int n_in,
                              void* d_out, int out_size)
{
    const float* x        = (const float*)d_in[0];  // (4096, 4096)
    const float* ln_scale = (const float*)d_in[1];  // (2048,)
    const float* W        = (const float*)d_in[2];  // (4096, 4096)
    const float* sb       = (const float*)d_in[3];  // (4096, 1)
    const float* pw       = (const float*)d_in[4];  // (2048, 1024)
    const float* pb       = (const float*)d_in[5];  // (1024,)
    float* out            = (float*)d_out;          // (4096, 1024)

    const int SP_SMEM = (2 * SP_AS_BUF + 2 * SP_BS_BUF) * 2;  // 54272 B
    const int PJ_SMEM = (2 * PJ_AS_BUF + 2 * PJ_BS_BUF) * 4;  // 71680 B
    cudaFuncSetAttribute(spatial_kernel,
                         cudaFuncAttributeMaxDynamicSharedMemorySize, SP_SMEM);
    cudaFuncSetAttribute(proj_kernel,
                         cudaFuncAttributeMaxDynamicSharedMemorySize, PJ_SMEM);

    ln_kernel<<<SEQ, 256>>>(x, ln_scale);
    pw_cvt_kernel<<<(DH * DOUT) / (256 * 4), 256>>>(pw);
    spatial_kernel<<<256, 512, SP_SMEM>>>(W, x, sb);
    proj_kernel<<<256, 256, PJ_SMEM>>>(pb, out);
}